// round 2
// baseline (speedup 1.0000x reference)
#include <cuda_runtime.h>
#include <cuda_bf16.h>
#include <cstdint>

// ---------------------------------------------------------------------------
// 6-slot ring of padded-NHWC bf16 activation buffers. Intra-slot offsets per
// resolution chosen so pool src/dst never overlap within a slot:
//   res64 @ 0          (32*66*66*256 = 35,684,352 elems)
//   res32 @ 35,684,352 (32*34*34*256 =  9,469,952)
//   res16 @ 0          (32*18*18*256 =  2,654,208)
//   res8  @ 4,000,000  (32*10*10*256 =    819,200)
// ---------------------------------------------------------------------------
#define SLOT_ELEMS 45154304ull
#define OFF64 0ull
#define OFF32 35684352ull
#define OFF16 0ull
#define OFF8  4000000ull

__device__ __align__(16) __nv_bfloat16 g_act[6][SLOT_ELEMS];
__device__ __align__(16) float         g_scratch[33554432];   // fp32 pre-BN [pixel][256]
__device__ __align__(16) __nv_bfloat16 g_w[9 * 256 * 256];    // [tap][cout][cin]
__device__ double g_sum[256];
__device__ double g_sqsum[256];
__device__ float  g_mu[256];
__device__ float  g_rstd[256];
__device__ float  g_feat[32 * 256];

// conv_w (OIHW fp32, already int/64) -> bf16 [tap][co][ci]
__global__ void k_prep_w(const float* __restrict__ cw) {
    int o = blockIdx.x * 256 + threadIdx.x;
    if (o >= 9 * 256 * 256) return;
    int tap = o >> 16;
    int r   = o & 65535;
    int co  = r >> 8, ci = r & 255;
    g_w[o] = __float2bfloat16(cw[((co << 8) + ci) * 9 + tap]);
}

// x (32,3,64,64) fp32 NCHW -> quantize (v=64), pad ch->256, padded NHWC bf16 slot0
__global__ void k_prep_in(const float* __restrict__ x) {
    long long e = (long long)blockIdx.x * 256 + threadIdx.x;
    if (e >= 35684352ll) return;
    int c = (int)(e & 255);
    long long r = e >> 8;
    int px = (int)(r % 66); r /= 66;
    int py = (int)(r % 66); int n = (int)(r / 66);
    float v = 0.f;
    if (py >= 1 && py <= 64 && px >= 1 && px <= 64 && c < 3) {
        float xv = x[(((long long)n * 3 + c) * 64 + (py - 1)) * 64 + (px - 1)];
        v = truncf(xv * 0.015625f) * 0.015625f;
    }
    g_act[0][e] = __float2bfloat16(v);
}

__global__ void k_zstat() {
    g_sum[threadIdx.x]   = 0.0;
    g_sqsum[threadIdx.x] = 0.0;
}

// ---------------------------------------------------------------------------
// conv3x3 implicit GEMM: M=64 pixels x N=64 couts per CTA, K=9*256.
// Epilogue fuses relu*alpha0 + history adds, fp32 scratch, channel stats.
// ---------------------------------------------------------------------------
#define LOADS(s) {                                                              \
    int tap_ = (s) >> 4, kc_ = (s) & 15;                                        \
    int ky_ = tap_ / 3, kx_ = tap_ - ky_ * 3;                                   \
    ra = *(const uint4*)(rowp[ky_] + kx_ * 256 + kc_ * 16);                     \
    rb = *(const uint4*)(g_w + tap_ * 65536 + (co0 + li) * 256 + kc_ * 16 + lci8); }

__global__ void __launch_bounds__(128) k_conv(
    int sPrev, int s1, int s2, int s3, int s4, int nhist,
    unsigned long long off, int H, int W,
    const float* __restrict__ alpha, int t)
{
    __shared__ __nv_bfloat16 As[2][64][24];
    __shared__ __nv_bfloat16 Bs[2][64][24];
    __shared__ float Csm[64][66];

    const int tid  = threadIdx.x;
    const int warp = tid >> 5, lane = tid & 31;
    const int g    = lane >> 2, qd = lane & 3;
    const int m_off = (warp & 1) * 32, n_off = (warp >> 1) * 32;
    const int p0 = blockIdx.x * 64, co0 = blockIdx.y * 64;

    const int li   = tid >> 1;
    const int lci8 = (tid & 1) * 8;
    const int HW = H * W;
    int p = p0 + li;
    int n = p / HW; int rem = p - n * HW;
    int y = rem / W; int x = rem - y * W;
    const int W2 = W + 2, H2 = H + 2;

    const __nv_bfloat16* hp = g_act[sPrev] + off;
    const __nv_bfloat16* rowp[3];
#pragma unroll
    for (int ky = 0; ky < 3; ky++)
        rowp[ky] = hp + (((long long)n * H2 + (y + ky)) * W2 + x) * 256 + lci8;

    float acc[2][4][4];
#pragma unroll
    for (int i = 0; i < 2; i++)
#pragma unroll
        for (int j = 0; j < 4; j++)
#pragma unroll
            for (int k = 0; k < 4; k++) acc[i][j][k] = 0.f;

    const int S = 144;
    uint4 ra, rb;
    LOADS(0);
    for (int s = 0; s < S; s++) {
        int b = s & 1;
        *(uint4*)&As[b][li][lci8] = ra;
        *(uint4*)&Bs[b][li][lci8] = rb;
        __syncthreads();
        if (s + 1 < S) LOADS(s + 1);

        unsigned av[2][4];
#pragma unroll
        for (int ms = 0; ms < 2; ms++) {
            int r0 = m_off + ms * 16 + g;
            av[ms][0] = *(const unsigned*)&As[b][r0][2 * qd];
            av[ms][1] = *(const unsigned*)&As[b][r0 + 8][2 * qd];
            av[ms][2] = *(const unsigned*)&As[b][r0][2 * qd + 8];
            av[ms][3] = *(const unsigned*)&As[b][r0 + 8][2 * qd + 8];
        }
#pragma unroll
        for (int ns = 0; ns < 4; ns++) {
            int rn = n_off + ns * 8 + g;
            unsigned b0 = *(const unsigned*)&Bs[b][rn][2 * qd];
            unsigned b1 = *(const unsigned*)&Bs[b][rn][2 * qd + 8];
#pragma unroll
            for (int ms = 0; ms < 2; ms++) {
                asm volatile(
                    "mma.sync.aligned.m16n8k16.row.col.f32.bf16.bf16.f32 "
                    "{%0,%1,%2,%3},{%4,%5,%6,%7},{%8,%9},{%0,%1,%2,%3};\n"
                    : "+f"(acc[ms][ns][0]), "+f"(acc[ms][ns][1]),
                      "+f"(acc[ms][ns][2]), "+f"(acc[ms][ns][3])
                    : "r"(av[ms][0]), "r"(av[ms][1]), "r"(av[ms][2]), "r"(av[ms][3]),
                      "r"(b0), "r"(b1));
            }
        }
        __syncthreads();
    }

#pragma unroll
    for (int ms = 0; ms < 2; ms++) {
        int r0 = m_off + ms * 16 + g;
#pragma unroll
        for (int ns = 0; ns < 4; ns++) {
            int cc = n_off + ns * 8 + 2 * qd;
            *(float2*)&Csm[r0][cc]     = make_float2(acc[ms][ns][0], acc[ms][ns][1]);
            *(float2*)&Csm[r0 + 8][cc] = make_float2(acc[ms][ns][2], acc[ms][ns][3]);
        }
    }
    __syncthreads();

    const float a0c = alpha[t * 6];
    int slots[4] = { s1, s2, s3, s4 };
    float coef[4];
    for (int d = 1; d <= nhist; d++) coef[d - 1] = alpha[t * 6 + 6 - d];
    long long hbase = (((long long)n * H2 + (y + 1)) * W2 + (x + 1)) * 256 + co0;
    int cb = (tid & 1) * 32;
    for (int c2 = 0; c2 < 32; c2++) {
        int col = cb + c2;
        float v = Csm[li][col];
        v = a0c * fmaxf(v, 0.f);
        for (int d = nhist; d >= 1; d--)
            v += coef[d - 1] * __bfloat162float(g_act[slots[d - 1]][off + hbase + col]);
        g_scratch[(long long)(p0 + li) * 256 + co0 + col] = v;
        Csm[li][col] = v;
    }
    __syncthreads();

    if (tid < 64) {
        double s = 0.0, sq = 0.0;
        for (int i = 0; i < 64; i++) {
            double vv = (double)Csm[i][tid];
            s += vv; sq += vv * vv;
        }
        atomicAdd(&g_sum[co0 + tid], s);
        atomicAdd(&g_sqsum[co0 + tid], sq);
    }
}

__global__ void k_stats(double invP) {
    int c = threadIdx.x;
    double mu  = g_sum[c] * invP;
    double var = g_sqsum[c] * invP - mu * mu;
    g_mu[c]   = (float)mu;
    g_rstd[c] = rsqrtf((float)var + 1e-5f);
}

// BN + trunc-quantize (v=64) -> padded NHWC bf16 (zero halo)
__global__ void k_bnq(int sd, unsigned long long doff, int H, int W,
                      const float* __restrict__ gamma, const float* __restrict__ beta)
{
    int W2 = W + 2, H2 = H + 2;
    long long total = (long long)32 * H2 * W2 * 128;
    long long e = (long long)blockIdx.x * 256 + threadIdx.x;
    if (e >= total) return;
    int cp = (int)(e & 127); int c = cp * 2;
    long long r = e >> 7;
    int px = (int)(r % W2); r /= W2;
    int py = (int)(r % H2); int n = (int)(r / H2);
    __nv_bfloat162 outv;
    if (py >= 1 && py <= H && px >= 1 && px <= W) {
        const float2 v = *(const float2*)&g_scratch[((((long long)n * H + (py - 1)) * W + (px - 1)) << 8) + c];
        float b0 = gamma[c]     * ((v.x - g_mu[c])     * g_rstd[c])     + beta[c];
        float b1 = gamma[c + 1] * ((v.y - g_mu[c + 1]) * g_rstd[c + 1]) + beta[c + 1];
        outv.x = __float2bfloat16(truncf(b0 * 0.015625f) * 0.015625f);
        outv.y = __float2bfloat16(truncf(b1 * 0.015625f) * 0.015625f);
    } else {
        outv.x = __float2bfloat16(0.f);
        outv.y = __float2bfloat16(0.f);
    }
    *(__nv_bfloat162*)(&g_act[sd][doff + (e << 1)]) = outv;
}

// 2x2 maxpool within a slot (src 2Hx2W -> dst HxW), padded->padded
__global__ void k_pool(int s, unsigned long long soff, unsigned long long doff, int H, int W)
{
    int W2 = W + 2, H2 = H + 2, SW2 = 2 * W + 2;
    long long total = (long long)32 * H2 * W2 * 128;
    long long e = (long long)blockIdx.x * 256 + threadIdx.x;
    if (e >= total) return;
    int cp = (int)(e & 127);
    long long r = e >> 7;
    int px = (int)(r % W2); r /= W2;
    int py = (int)(r % H2); int n = (int)(r / H2);
    __nv_bfloat162 o;
    if (py >= 1 && py <= H && px >= 1 && px <= W) {
        const __nv_bfloat16* base = g_act[s] + soff;
        long long i00 = (((long long)n * (2 * H + 2) + (2 * py - 1)) * SW2 + (2 * px - 1)) * 256 + cp * 2;
        long long rs = (long long)SW2 * 256;
        __nv_bfloat162 v00 = *(const __nv_bfloat162*)(base + i00);
        __nv_bfloat162 v01 = *(const __nv_bfloat162*)(base + i00 + 256);
        __nv_bfloat162 v10 = *(const __nv_bfloat162*)(base + i00 + rs);
        __nv_bfloat162 v11 = *(const __nv_bfloat162*)(base + i00 + rs + 256);
        float m0 = fmaxf(fmaxf(__bfloat162float(v00.x), __bfloat162float(v01.x)),
                         fmaxf(__bfloat162float(v10.x), __bfloat162float(v11.x)));
        float m1 = fmaxf(fmaxf(__bfloat162float(v00.y), __bfloat162float(v01.y)),
                         fmaxf(__bfloat162float(v10.y), __bfloat162float(v11.y)));
        o.x = __float2bfloat16(m0);
        o.y = __float2bfloat16(m1);
    } else {
        o.x = __float2bfloat16(0.f);
        o.y = __float2bfloat16(0.f);
    }
    *(__nv_bfloat162*)(g_act[s] + doff + (e << 1)) = o;
}

__global__ void k_feat(int s, unsigned long long off) {
    int id = blockIdx.x * 256 + threadIdx.x;    // 32*256
    int n = id >> 8, c = id & 255;
    const __nv_bfloat16* base = g_act[s] + off;
    float m = -3.4e38f;
    for (int yy = 0; yy < 8; yy++)
        for (int xx = 0; xx < 8; xx++) {
            float v = __bfloat162float(base[(((long long)n * 10 + (yy + 1)) * 10 + (xx + 1)) * 256 + c]);
            m = fmaxf(m, v);
        }
    g_feat[id] = m;
}

__global__ void k_lin(const float* __restrict__ lw, const float* __restrict__ lb,
                      float* __restrict__ out) {
    __shared__ float fs[256];
    int n = blockIdx.y;
    int cls = blockIdx.x * 256 + threadIdx.x;
    fs[threadIdx.x] = g_feat[n * 256 + threadIdx.x];
    __syncthreads();
    if (cls < 1000) {
        float a = 0.f;
#pragma unroll 8
        for (int c = 0; c < 256; c++) a += fs[c] * lw[cls * 256 + c];
        out[n * 1000 + cls] = a + lb[cls];
    }
}

// ---------------------------------------------------------------------------
extern "C" void kernel_launch(void* const* d_in, const int* in_sizes, int n_in,
                              void* d_out, int out_size)
{
    const float* x      = (const float*)d_in[0];
    const float* conv_w = (const float*)d_in[1];
    const float* lin_w  = (const float*)d_in[2];
    const float* lin_b  = (const float*)d_in[3];
    const float* alpha  = (const float*)d_in[4];
    const float* gmm    = (const float*)d_in[5];
    const float* bta    = (const float*)d_in[6];
    float* out = (float*)d_out;

    k_prep_w<<<2304, 256>>>(conv_w);
    k_prep_in<<<139392, 256>>>(x);

    // slot schedule: a_t -> slot (t+1)%6; hist newest..oldest = S1..S4
    static const int S1[10]  = {0,1,2,3,4,5,0,1,2,3};
    static const int S2[10]  = {0,0,1,2,3,4,5,0,1,2};
    static const int S3[10]  = {0,0,0,1,2,3,4,5,0,1};
    static const int S4[10]  = {0,0,0,0,1,2,3,4,5,0};
    static const int NH[10]  = {1,2,3,4,4,4,4,4,4,4};
    static const int DST[10] = {1,2,3,4,5,0,1,2,3,4};
    static const int HH[10]  = {64,64,64,32,32,32,16,16,16,8};
    static const unsigned long long OFFT[10] =
        {OFF64,OFF64,OFF64,OFF32,OFF32,OFF32,OFF16,OFF16,OFF16,OFF8};

    for (int t = 0; t < 10; t++) {
        int H = HH[t], W = H, P = 32 * H * W;
        unsigned long long off = OFFT[t];
        k_zstat<<<1, 256>>>();
        dim3 cg(P / 64, 4);
        k_conv<<<cg, 128>>>(S1[t], S1[t], S2[t], S3[t], S4[t], NH[t], off, H, W, alpha, t);
        k_stats<<<1, 256>>>(1.0 / (double)P);
        long long tot = (long long)32 * (H + 2) * (W + 2) * 128;
        k_bnq<<<(unsigned)((tot + 255) / 256), 256>>>(DST[t], off, H, W,
                                                      gmm + t * 256, bta + t * 256);
        if (t == 2 || t == 5 || t == 8) {
            int Hd = H / 2, Wd = Hd;
            unsigned long long soff = off;
            unsigned long long doff = (t == 2) ? OFF32 : (t == 5) ? OFF16 : OFF8;
            long long pt = (long long)32 * (Hd + 2) * (Wd + 2) * 128;
            int ps[4];
            if (t == 2)      { ps[0]=0; ps[1]=1; ps[2]=2; ps[3]=3; }
            else if (t == 5) { ps[0]=3; ps[1]=4; ps[2]=5; ps[3]=0; }
            else             { ps[0]=0; ps[1]=1; ps[2]=2; ps[3]=3; }
            for (int j = 0; j < 4; j++)
                k_pool<<<(unsigned)((pt + 255) / 256), 256>>>(ps[j], soff, doff, Hd, Wd);
        }
    }
    k_feat<<<32, 256>>>(4, OFF8);
    k_lin<<<dim3(4, 32), 256>>>(lin_w, lin_b, out);
}

// round 3
// speedup vs baseline: 2.0490x; 2.0490x over previous
#include <cuda_runtime.h>
#include <cuda_bf16.h>
#include <cstdint>

// ---------------------------------------------------------------------------
// 6-slot ring of padded-NHWC bf16 activation buffers.
//   res64 @ 0          (32*66*66*256 = 35,684,352 elems)
//   res32 @ 35,684,352 (32*34*34*256 =  9,469,952)
//   res16 @ 0          (32*18*18*256 =  2,654,208)
//   res8  @ 4,000,000  (32*10*10*256 =    819,200)
// ---------------------------------------------------------------------------
#define SLOT_ELEMS 45154304ull
#define OFF64 0ull
#define OFF32 35684352ull
#define OFF16 0ull
#define OFF8  4000000ull

__device__ __align__(16) __nv_bfloat16 g_act[6][SLOT_ELEMS];
__device__ __align__(16) float         g_scratch[33554432];   // fp32 pre-BN [pixel][256]
__device__ __align__(16) uint2         g_wf[147456];          // [tap][kc][nb][lane] B fragments
__device__ double g_sum[256];
__device__ double g_sqsum[256];
__device__ float  g_mu[256];
__device__ float  g_rstd[256];
__device__ float  g_feat[32 * 256];

__device__ __forceinline__ unsigned su32(const void* p) {
    return (unsigned)__cvta_generic_to_shared(p);
}

// conv_w (OIHW fp32, values = int/64) -> B-fragment layout:
// g_wf[((tap*16+kc)*32+nb)*32+lane] = {B[co=nb*8+g][k=kc*16+2qd..+1], [..+8..+9]}
__global__ void k_prep_w(const float* __restrict__ cw) {
    int idx = blockIdx.x * 256 + threadIdx.x;
    if (idx >= 147456) return;
    int l   = idx & 31;
    int nb  = (idx >> 5) & 31;
    int kc  = (idx >> 10) & 15;
    int tap = idx >> 14;
    int g = l >> 2, qd = l & 3;
    int co = nb * 8 + g, ci0 = kc * 16 + 2 * qd;
    __nv_bfloat162 lo, hi;
    lo.x = __float2bfloat16(cw[(co * 256 + ci0    ) * 9 + tap]);
    lo.y = __float2bfloat16(cw[(co * 256 + ci0 + 1) * 9 + tap]);
    hi.x = __float2bfloat16(cw[(co * 256 + ci0 + 8) * 9 + tap]);
    hi.y = __float2bfloat16(cw[(co * 256 + ci0 + 9) * 9 + tap]);
    uint2 v;
    v.x = *(unsigned*)&lo;
    v.y = *(unsigned*)&hi;
    g_wf[idx] = v;
}

// x (32,3,64,64) fp32 NCHW -> quantize (v=64), pad ch->256, padded NHWC bf16 slot0
__global__ void k_prep_in(const float* __restrict__ x) {
    long long e = (long long)blockIdx.x * 256 + threadIdx.x;
    if (e >= 35684352ll) return;
    int c = (int)(e & 255);
    long long r = e >> 8;
    int px = (int)(r % 66); r /= 66;
    int py = (int)(r % 66); int n = (int)(r / 66);
    float v = 0.f;
    if (py >= 1 && py <= 64 && px >= 1 && px <= 64 && c < 3) {
        float xv = x[(((long long)n * 3 + c) * 64 + (py - 1)) * 64 + (px - 1)];
        v = truncf(xv * 0.015625f) * 0.015625f;
    }
    g_act[0][e] = __float2bfloat16(v);
}

__global__ void k_zstat() {
    g_sum[threadIdx.x]   = 0.0;
    g_sqsum[threadIdx.x] = 0.0;
}

// ---------------------------------------------------------------------------
// conv3x3 implicit GEMM. CTA: MT pixels x 64 couts, K=2304.
// A: cp.async -> swizzled smem -> ldmatrix.x4.  B: fragment-direct LDG.64 (L2).
// Epilogue in registers: relu*a0 + history adds, scratch write, channel stats.
// ---------------------------------------------------------------------------
#define MMA_(c, a, b)                                                           \
    asm volatile("mma.sync.aligned.m16n8k16.row.col.f32.bf16.bf16.f32 "         \
                 "{%0,%1,%2,%3},{%4,%5,%6,%7},{%8,%9},{%0,%1,%2,%3};\n"         \
                 : "+f"(c[0]), "+f"(c[1]), "+f"(c[2]), "+f"(c[3])               \
                 : "r"(a[0]), "r"(a[1]), "r"(a[2]), "r"(a[3]),                  \
                   "r"(b.x), "r"(b.y))

template <int MT>
__global__ void __launch_bounds__(MT * 2) k_conv(
    int sPrev, int s1, int s2, int s3, int s4, int nhist,
    unsigned long long off, int lw,
    const float* __restrict__ alpha, int t)
{
    constexpr int S   = 144;
    constexpr int MW  = MT / 32;
    constexpr int STB = MT * 32;               // stage bytes
    __shared__ __align__(256) char As[3 * STB];
    __shared__ float s_sum[64], s_sq[64];

    const int tid = threadIdx.x, warp = tid >> 5, lane = tid & 31;
    const int g = lane >> 2, qd = lane & 3;
    const int mw = warp % MW, nw = warp / MW;
    const int m_off = mw * 32, n_off = nw * 32;
    const int p0 = blockIdx.x * MT, co0 = blockIdx.y * 64;
    const int W = 1 << lw, W2 = W + 2;

    if (tid < 64) { s_sum[tid] = 0.f; s_sq[tid] = 0.f; }

    // --- cp.async per-thread source (row r, 16B-half h) ---
    const int r = tid >> 1, h = tid & 1;
    {
    }
    int p  = p0 + r;
    int n  = p >> (2 * lw);
    int rm = p & ((1 << (2 * lw)) - 1);
    int yy = rm >> lw, xx = rm & (W - 1);
    const __nv_bfloat16* hp = g_act[sPrev] + off;
    const __nv_bfloat16* rowp[3];
#pragma unroll
    for (int ky = 0; ky < 3; ky++)
        rowp[ky] = hp + ((long long)(n * W2 + yy + ky) * W2 + xx) * 256 + h * 8;

    const int rr = r & 7;
    const unsigned dstb = su32(As) + (r >> 3) * 256 + ((rr * 2 + (h ^ ((rr >> 2) & 1))) << 4);

    // --- ldmatrix per-lane smem offset (ms=0; ms=1 is +512B) ---
    const int rl = m_off + (lane & 15), hh = lane >> 4, rlr = rl & 7;
    const unsigned ldsb = su32(As) + (rl >> 3) * 256 + ((rlr * 2 + (hh ^ ((rlr >> 2) & 1))) << 4);

    const int nb0 = (co0 >> 3) + nw * 4;

#define CPA(s_) {                                                               \
    int tap_ = (s_) >> 4, kc_ = (s_) & 15;                                      \
    int ky_ = tap_ / 3, kx_ = tap_ - ky_ * 3;                                   \
    const void* src_ = (const void*)(rowp[ky_] + kx_ * 256 + kc_ * 16);         \
    unsigned d_ = dstb + ((s_) % 3) * STB;                                      \
    asm volatile("cp.async.cg.shared.global [%0],[%1],16;\n" :: "r"(d_), "l"(src_)); \
    asm volatile("cp.async.commit_group;\n"); }

#define LDB(dst, s_) {                                                          \
    const uint2* wp_ = g_wf + (((s_) * 32 + nb0) << 5) + lane;                  \
    dst[0] = wp_[0]; dst[1] = wp_[32]; dst[2] = wp_[64]; dst[3] = wp_[96]; }

    float acc[2][4][4];
#pragma unroll
    for (int i = 0; i < 2; i++)
#pragma unroll
        for (int j = 0; j < 4; j++)
#pragma unroll
            for (int k = 0; k < 4; k++) acc[i][j][k] = 0.f;

    uint2 bc[4], bn_[4];
    CPA(0); CPA(1);
    LDB(bc, 0);

    for (int s = 0; s < S; s++) {
        if (s == S - 1) asm volatile("cp.async.wait_group 0;\n" ::);
        else            asm volatile("cp.async.wait_group 1;\n" ::);
        __syncthreads();
        if (s + 2 < S) CPA(s + 2);
        if (s + 1 < S) LDB(bn_, s + 1);

        unsigned base = ldsb + (s % 3) * STB;
        unsigned a0[4], a1[4];
        asm volatile("ldmatrix.sync.aligned.m8n8.x4.shared.b16 {%0,%1,%2,%3},[%4];\n"
                     : "=r"(a0[0]), "=r"(a0[1]), "=r"(a0[2]), "=r"(a0[3]) : "r"(base));
        asm volatile("ldmatrix.sync.aligned.m8n8.x4.shared.b16 {%0,%1,%2,%3},[%4];\n"
                     : "=r"(a1[0]), "=r"(a1[1]), "=r"(a1[2]), "=r"(a1[3]) : "r"(base + 512));
#pragma unroll
        for (int ns = 0; ns < 4; ns++) {
            MMA_(acc[0][ns], a0, bc[ns]);
            MMA_(acc[1][ns], a1, bc[ns]);
        }
#pragma unroll
        for (int j = 0; j < 4; j++) bc[j] = bn_[j];
    }

    // ---- register-space epilogue ----
    const float a0c = alpha[t * 6];
    int slots[4] = { s1, s2, s3, s4 };
    float coef[4] = { 0.f, 0.f, 0.f, 0.f };
    for (int d = 1; d <= nhist; d++) coef[d - 1] = alpha[t * 6 + 6 - d];

    float cs[8], cq[8];
#pragma unroll
    for (int j = 0; j < 8; j++) { cs[j] = 0.f; cq[j] = 0.f; }

#pragma unroll
    for (int ms = 0; ms < 2; ms++) {
#pragma unroll
        for (int half = 0; half < 2; half++) {
            int pe  = p0 + m_off + ms * 16 + g + half * 8;
            int ne  = pe >> (2 * lw);
            int rme = pe & ((1 << (2 * lw)) - 1);
            int ye = rme >> lw, xe = rme & (W - 1);
            long long hb = (long long)off + ((long long)(ne * W2 + ye + 1) * W2 + xe + 1) * 256
                           + co0 + n_off + 2 * qd;
            long long sb = (long long)pe * 256 + co0 + n_off + 2 * qd;
#pragma unroll
            for (int ns = 0; ns < 4; ns++) {
                float v0 = a0c * fmaxf(acc[ms][ns][half * 2 + 0], 0.f);
                float v1 = a0c * fmaxf(acc[ms][ns][half * 2 + 1], 0.f);
                for (int d = nhist; d >= 1; d--) {
                    __nv_bfloat162 hv = *(const __nv_bfloat162*)&g_act[slots[d - 1]][hb + ns * 8];
                    v0 += coef[d - 1] * __bfloat162float(hv.x);
                    v1 += coef[d - 1] * __bfloat162float(hv.y);
                }
                *(float2*)&g_scratch[sb + ns * 8] = make_float2(v0, v1);
                cs[ns * 2 + 0] += v0; cs[ns * 2 + 1] += v1;
                cq[ns * 2 + 0] += v0 * v0; cq[ns * 2 + 1] += v1 * v1;
            }
        }
    }
#pragma unroll
    for (int m = 4; m < 32; m <<= 1) {
#pragma unroll
        for (int j = 0; j < 8; j++) {
            cs[j] += __shfl_xor_sync(0xffffffffu, cs[j], m);
            cq[j] += __shfl_xor_sync(0xffffffffu, cq[j], m);
        }
    }
    if (lane < 4) {
#pragma unroll
        for (int ns = 0; ns < 4; ns++) {
            int ch = n_off + ns * 8 + 2 * lane;
            atomicAdd(&s_sum[ch],     cs[ns * 2 + 0]);
            atomicAdd(&s_sum[ch + 1], cs[ns * 2 + 1]);
            atomicAdd(&s_sq[ch],      cq[ns * 2 + 0]);
            atomicAdd(&s_sq[ch + 1],  cq[ns * 2 + 1]);
        }
    }
    __syncthreads();
    if (tid < 64) {
        atomicAdd(&g_sum[co0 + tid],   (double)s_sum[tid]);
        atomicAdd(&g_sqsum[co0 + tid], (double)s_sq[tid]);
    }
#undef CPA
#undef LDB
}

__global__ void k_stats(double invP) {
    int c = threadIdx.x;
    double mu  = g_sum[c] * invP;
    double var = g_sqsum[c] * invP - mu * mu;
    g_mu[c]   = (float)mu;
    g_rstd[c] = rsqrtf((float)var + 1e-5f);
}

// BN + trunc-quantize (v=64) -> padded NHWC bf16 (zero halo)
__global__ void k_bnq(int sd, unsigned long long doff, int H, int W,
                      const float* __restrict__ gamma, const float* __restrict__ beta)
{
    int W2 = W + 2, H2 = H + 2;
    long long total = (long long)32 * H2 * W2 * 128;
    long long e = (long long)blockIdx.x * 256 + threadIdx.x;
    if (e >= total) return;
    int cp = (int)(e & 127); int c = cp * 2;
    long long r = e >> 7;
    int px = (int)(r % W2); r /= W2;
    int py = (int)(r % H2); int n = (int)(r / H2);
    __nv_bfloat162 outv;
    if (py >= 1 && py <= H && px >= 1 && px <= W) {
        const float2 v = *(const float2*)&g_scratch[((((long long)n * H + (py - 1)) * W + (px - 1)) << 8) + c];
        float b0 = gamma[c]     * ((v.x - g_mu[c])     * g_rstd[c])     + beta[c];
        float b1 = gamma[c + 1] * ((v.y - g_mu[c + 1]) * g_rstd[c + 1]) + beta[c + 1];
        outv.x = __float2bfloat16(truncf(b0 * 0.015625f) * 0.015625f);
        outv.y = __float2bfloat16(truncf(b1 * 0.015625f) * 0.015625f);
    } else {
        outv.x = __float2bfloat16(0.f);
        outv.y = __float2bfloat16(0.f);
    }
    *(__nv_bfloat162*)(&g_act[sd][doff + (e << 1)]) = outv;
}

// 2x2 maxpool within a slot (src 2Hx2W -> dst HxW), padded->padded
__global__ void k_pool(int s, unsigned long long soff, unsigned long long doff, int H, int W)
{
    int W2 = W + 2, H2 = H + 2, SW2 = 2 * W + 2;
    long long total = (long long)32 * H2 * W2 * 128;
    long long e = (long long)blockIdx.x * 256 + threadIdx.x;
    if (e >= total) return;
    int cp = (int)(e & 127);
    long long r = e >> 7;
    int px = (int)(r % W2); r /= W2;
    int py = (int)(r % H2); int n = (int)(r / H2);
    __nv_bfloat162 o;
    if (py >= 1 && py <= H && px >= 1 && px <= W) {
        const __nv_bfloat16* base = g_act[s] + soff;
        long long i00 = (((long long)n * (2 * H + 2) + (2 * py - 1)) * SW2 + (2 * px - 1)) * 256 + cp * 2;
        long long rs = (long long)SW2 * 256;
        __nv_bfloat162 v00 = *(const __nv_bfloat162*)(base + i00);
        __nv_bfloat162 v01 = *(const __nv_bfloat162*)(base + i00 + 256);
        __nv_bfloat162 v10 = *(const __nv_bfloat162*)(base + i00 + rs);
        __nv_bfloat162 v11 = *(const __nv_bfloat162*)(base + i00 + rs + 256);
        float m0 = fmaxf(fmaxf(__bfloat162float(v00.x), __bfloat162float(v01.x)),
                         fmaxf(__bfloat162float(v10.x), __bfloat162float(v11.x)));
        float m1 = fmaxf(fmaxf(__bfloat162float(v00.y), __bfloat162float(v01.y)),
                         fmaxf(__bfloat162float(v10.y), __bfloat162float(v11.y)));
        o.x = __float2bfloat16(m0);
        o.y = __float2bfloat16(m1);
    } else {
        o.x = __float2bfloat16(0.f);
        o.y = __float2bfloat16(0.f);
    }
    *(__nv_bfloat162*)(g_act[s] + doff + (e << 1)) = o;
}

__global__ void k_feat(int s, unsigned long long off) {
    int id = blockIdx.x * 256 + threadIdx.x;    // 32*256
    int n = id >> 8, c = id & 255;
    const __nv_bfloat16* base = g_act[s] + off;
    float m = -3.4e38f;
    for (int yy = 0; yy < 8; yy++)
        for (int xx = 0; xx < 8; xx++) {
            float v = __bfloat162float(base[(((long long)n * 10 + (yy + 1)) * 10 + (xx + 1)) * 256 + c]);
            m = fmaxf(m, v);
        }
    g_feat[id] = m;
}

__global__ void k_lin(const float* __restrict__ lw, const float* __restrict__ lb,
                      float* __restrict__ out) {
    __shared__ float fs[256];
    int n = blockIdx.y;
    int cls = blockIdx.x * 256 + threadIdx.x;
    fs[threadIdx.x] = g_feat[n * 256 + threadIdx.x];
    __syncthreads();
    if (cls < 1000) {
        float a = 0.f;
#pragma unroll 8
        for (int c = 0; c < 256; c++) a += fs[c] * lw[cls * 256 + c];
        out[n * 1000 + cls] = a + lb[cls];
    }
}

// ---------------------------------------------------------------------------
extern "C" void kernel_launch(void* const* d_in, const int* in_sizes, int n_in,
                              void* d_out, int out_size)
{
    const float* x      = (const float*)d_in[0];
    const float* conv_w = (const float*)d_in[1];
    const float* lin_w  = (const float*)d_in[2];
    const float* lin_b  = (const float*)d_in[3];
    const float* alpha  = (const float*)d_in[4];
    const float* gmm    = (const float*)d_in[5];
    const float* bta    = (const float*)d_in[6];
    float* out = (float*)d_out;

    k_prep_w<<<576, 256>>>(conv_w);
    k_prep_in<<<139392, 256>>>(x);

    static const int S1[10]  = {0,1,2,3,4,5,0,1,2,3};
    static const int S2[10]  = {0,0,1,2,3,4,5,0,1,2};
    static const int S3[10]  = {0,0,0,1,2,3,4,5,0,1};
    static const int S4[10]  = {0,0,0,0,1,2,3,4,5,0};
    static const int NH[10]  = {1,2,3,4,4,4,4,4,4,4};
    static const int DST[10] = {1,2,3,4,5,0,1,2,3,4};
    static const int HH[10]  = {64,64,64,32,32,32,16,16,16,8};
    static const int LW[10]  = {6,6,6,5,5,5,4,4,4,3};
    static const unsigned long long OFFT[10] =
        {OFF64,OFF64,OFF64,OFF32,OFF32,OFF32,OFF16,OFF16,OFF16,OFF8};

    for (int t = 0; t < 10; t++) {
        int H = HH[t], W = H, P = 32 * H * W;
        unsigned long long off = OFFT[t];
        k_zstat<<<1, 256>>>();
        if (P >= 8192) {
            dim3 cg(P / 128, 4);
            k_conv<128><<<cg, 256>>>(S1[t], S1[t], S2[t], S3[t], S4[t], NH[t],
                                     off, LW[t], alpha, t);
        } else {
            dim3 cg(P / 64, 4);
            k_conv<64><<<cg, 128>>>(S1[t], S1[t], S2[t], S3[t], S4[t], NH[t],
                                    off, LW[t], alpha, t);
        }
        k_stats<<<1, 256>>>(1.0 / (double)P);
        long long tot = (long long)32 * (H + 2) * (W + 2) * 128;
        k_bnq<<<(unsigned)((tot + 255) / 256), 256>>>(DST[t], off, H, W,
                                                      gmm + t * 256, bta + t * 256);
        if (t == 2 || t == 5 || t == 8) {
            int Hd = H / 2, Wd = Hd;
            unsigned long long soff = off;
            unsigned long long doff = (t == 2) ? OFF32 : (t == 5) ? OFF16 : OFF8;
            long long pt = (long long)32 * (Hd + 2) * (Wd + 2) * 128;
            int ps[4];
            if (t == 2)      { ps[0]=0; ps[1]=1; ps[2]=2; ps[3]=3; }
            else if (t == 5) { ps[0]=3; ps[1]=4; ps[2]=5; ps[3]=0; }
            else             { ps[0]=0; ps[1]=1; ps[2]=2; ps[3]=3; }
            for (int j = 0; j < 4; j++)
                k_pool<<<(unsigned)((pt + 255) / 256), 256>>>(ps[j], soff, doff, Hd, Wd);
        }
    }
    k_feat<<<32, 256>>>(4, OFF8);
    k_lin<<<dim3(4, 32), 256>>>(lin_w, lin_b, out);
}

// round 4
// speedup vs baseline: 2.6935x; 1.3145x over previous
#include <cuda_runtime.h>
#include <cuda_bf16.h>
#include <cstdint>

// ---------------------------------------------------------------------------
// 6-slot ring of padded-NHWC bf16 activation buffers.
//   res64 @ 0, res32 @ 35,684,352, res16 @ 0, res8 @ 4,000,000
// ---------------------------------------------------------------------------
#define SLOT_ELEMS 45154304ull
#define OFF64 0ull
#define OFF32 35684352ull
#define OFF16 0ull
#define OFF8  4000000ull

__device__ __align__(16) __nv_bfloat16 g_act[6][SLOT_ELEMS];
__device__ __align__(16) float         g_scratch[33554432];   // fp32 pre-BN [pixel][256]
__device__ __align__(16) uint2         g_wf[147456];          // [tap][kc][nb][lane] B fragments
__device__ double g_sum[256];
__device__ double g_sqsum[256];
__device__ float  g_mu[256];
__device__ float  g_rstd[256];
__device__ float  g_feat[32 * 256];

__device__ __forceinline__ unsigned su32(const void* p) {
    return (unsigned)__cvta_generic_to_shared(p);
}

// conv_w (OIHW fp32, values = int/64) -> B-fragment layout:
// g_wf[((tap*16+kc)*32+nb)*32+lane] = {B[co=nb*8+g][k=kc*16+2qd..+1], [..+8..+9]}
__global__ void k_prep_w(const float* __restrict__ cw) {
    int idx = blockIdx.x * 256 + threadIdx.x;
    if (idx < 256) { g_sum[idx] = 0.0; g_sqsum[idx] = 0.0; }
    if (idx >= 147456) return;
    int l   = idx & 31;
    int nb  = (idx >> 5) & 31;
    int kc  = (idx >> 10) & 15;
    int tap = idx >> 14;
    int g = l >> 2, qd = l & 3;
    int co = nb * 8 + g, ci0 = kc * 16 + 2 * qd;
    __nv_bfloat162 lo, hi;
    lo.x = __float2bfloat16(cw[(co * 256 + ci0    ) * 9 + tap]);
    lo.y = __float2bfloat16(cw[(co * 256 + ci0 + 1) * 9 + tap]);
    hi.x = __float2bfloat16(cw[(co * 256 + ci0 + 8) * 9 + tap]);
    hi.y = __float2bfloat16(cw[(co * 256 + ci0 + 9) * 9 + tap]);
    uint2 v;
    v.x = *(unsigned*)&lo;
    v.y = *(unsigned*)&hi;
    g_wf[idx] = v;
}

// x (32,3,64,64) fp32 NCHW -> quantize (v=64), pad ch->256, padded NHWC bf16 slot0
__global__ void k_prep_in(const float* __restrict__ x) {
    long long e = (long long)blockIdx.x * 256 + threadIdx.x;
    if (e >= 35684352ll) return;
    int c = (int)(e & 255);
    long long r = e >> 8;
    int px = (int)(r % 66); r /= 66;
    int py = (int)(r % 66); int n = (int)(r / 66);
    float v = 0.f;
    if (py >= 1 && py <= 64 && px >= 1 && px <= 64 && c < 3) {
        float xv = x[(((long long)n * 3 + c) * 64 + (py - 1)) * 64 + (px - 1)];
        v = truncf(xv * 0.015625f) * 0.015625f;
    }
    g_act[0][e] = __float2bfloat16(v);
}

// ---------------------------------------------------------------------------
// conv3x3 implicit GEMM. CTA: 128 pixels x 128 couts, 8 warps (4M x 2N),
// warp tile M32 x N64 -> 16 MMA per k16 stage. K = 2304 (144 stages).
// A: cp.async -> swizzled smem -> ldmatrix.x4.  B: fragment LDG.64 (L2).
// ---------------------------------------------------------------------------
#define MMA_(c, a, b)                                                           \
    asm volatile("mma.sync.aligned.m16n8k16.row.col.f32.bf16.bf16.f32 "         \
                 "{%0,%1,%2,%3},{%4,%5,%6,%7},{%8,%9},{%0,%1,%2,%3};\n"         \
                 : "+f"(c[0]), "+f"(c[1]), "+f"(c[2]), "+f"(c[3])               \
                 : "r"(a[0]), "r"(a[1]), "r"(a[2]), "r"(a[3]),                  \
                   "r"(b.x), "r"(b.y))

__global__ void __launch_bounds__(256, 2) k_conv(
    int sPrev, int s1, int s2, int s3, int s4, int nhist,
    unsigned long long off, int lw,
    const float* __restrict__ alpha, int t)
{
    constexpr int S   = 144;
    constexpr int STB = 4096;                  // stage bytes: 128 rows x 32B
    __shared__ __align__(256) char As[3 * STB];
    __shared__ float s_sum[128], s_sq[128];

    const int tid = threadIdx.x, warp = tid >> 5, lane = tid & 31;
    const int g = lane >> 2, qd = lane & 3;
    const int mw = warp >> 1, nw = warp & 1;
    const int m_off = mw * 32, n_off = nw * 64;
    const int p0 = blockIdx.x * 128, co0 = blockIdx.y * 128;
    const int W = 1 << lw, W2 = W + 2;

    if (tid < 128) { s_sum[tid] = 0.f; s_sq[tid] = 0.f; }

    // cp.async per-thread source (row r, 16B-half h)
    const int r = tid >> 1, h = tid & 1;
    int p  = p0 + r;
    int n  = p >> (2 * lw);
    int rm = p & ((1 << (2 * lw)) - 1);
    int yy = rm >> lw, xx = rm & (W - 1);
    const __nv_bfloat16* hp = g_act[sPrev] + off;
    const char* rowp[3];
#pragma unroll
    for (int ky = 0; ky < 3; ky++)
        rowp[ky] = (const char*)(hp + ((long long)(n * W2 + yy + ky) * W2 + xx) * 256 + h * 8);

    const int rr = r & 7;
    const unsigned dstb = su32(As) + (r >> 3) * 256 + ((rr * 2 + (h ^ ((rr >> 2) & 1))) << 4);

    // ldmatrix per-lane smem offset (second m16 is +512B)
    const int rl = m_off + (lane & 15), hh = lane >> 4, rlr = rl & 7;
    const unsigned ldsb = su32(As) + (rl >> 3) * 256 + ((rlr * 2 + (hh ^ ((rlr >> 2) & 1))) << 4);

    const int nb0 = (co0 >> 3) + nw * 8;

#define CPA(s_, ph_) {                                                          \
    int tap_ = (s_) >> 4, kc_ = (s_) & 15;                                      \
    int ky_ = (tap_ * 11) >> 5; int kx_ = tap_ - 3 * ky_;                       \
    const char* src_ = rowp[ky_] + kx_ * 512 + kc_ * 32;                        \
    asm volatile("cp.async.cg.shared.global [%0],[%1],16;\n"                    \
                 :: "r"(dstb + (ph_) * STB), "l"(src_));                        \
    asm volatile("cp.async.commit_group;\n"); }

#define LDB(dst) {                                                              \
    dst[0] = wptr[0];   dst[1] = wptr[32];  dst[2] = wptr[64];  dst[3] = wptr[96]; \
    dst[4] = wptr[128]; dst[5] = wptr[160]; dst[6] = wptr[192]; dst[7] = wptr[224]; \
    wptr += 1024; }

    float acc[2][8][4];
#pragma unroll
    for (int i = 0; i < 2; i++)
#pragma unroll
        for (int j = 0; j < 8; j++)
#pragma unroll
            for (int k = 0; k < 4; k++) acc[i][j][k] = 0.f;

    uint2 bA[8], bB[8];
    const uint2* wptr = g_wf + (nb0 << 5) + lane;
    LDB(bA);
    CPA(0, 0); CPA(1, 1);

#define BODY(j_, CUR, NXT) {                                                    \
    int s_ = sb + (j_);                                                         \
    if (s_ == S - 1) asm volatile("cp.async.wait_group 0;\n" ::);               \
    else             asm volatile("cp.async.wait_group 1;\n" ::);               \
    __syncthreads();                                                            \
    if (s_ + 2 < S) CPA(s_ + 2, ((j_) + 2) % 3);                                \
    if (s_ + 1 < S) LDB(NXT);                                                   \
    unsigned a0[4], a1[4];                                                      \
    unsigned base_ = ldsb + ((j_) % 3) * STB;                                   \
    asm volatile("ldmatrix.sync.aligned.m8n8.x4.shared.b16 {%0,%1,%2,%3},[%4];\n" \
                 : "=r"(a0[0]), "=r"(a0[1]), "=r"(a0[2]), "=r"(a0[3]) : "r"(base_)); \
    asm volatile("ldmatrix.sync.aligned.m8n8.x4.shared.b16 {%0,%1,%2,%3},[%4];\n" \
                 : "=r"(a1[0]), "=r"(a1[1]), "=r"(a1[2]), "=r"(a1[3]) : "r"(base_ + 512)); \
    _Pragma("unroll")                                                           \
    for (int ns = 0; ns < 8; ns++) {                                            \
        MMA_(acc[0][ns], a0, CUR[ns]);                                          \
        MMA_(acc[1][ns], a1, CUR[ns]);                                          \
    } }

    for (int sb = 0; sb < S; sb += 6) {
        BODY(0, bA, bB); BODY(1, bB, bA); BODY(2, bA, bB);
        BODY(3, bB, bA); BODY(4, bA, bB); BODY(5, bB, bA);
    }
#undef BODY
#undef CPA
#undef LDB

    // ---- register-space epilogue ----
    const float a0c = alpha[t * 6];
    int slots[4] = { s1, s2, s3, s4 };
    float coef[4] = { 0.f, 0.f, 0.f, 0.f };
    for (int d = 1; d <= nhist; d++) coef[d - 1] = alpha[t * 6 + 6 - d];

    float cs[16], cq[16];
#pragma unroll
    for (int j = 0; j < 16; j++) { cs[j] = 0.f; cq[j] = 0.f; }

#pragma unroll
    for (int ms = 0; ms < 2; ms++) {
#pragma unroll
        for (int half = 0; half < 2; half++) {
            int pe  = p0 + m_off + ms * 16 + g + half * 8;
            int ne  = pe >> (2 * lw);
            int rme = pe & ((1 << (2 * lw)) - 1);
            int ye = rme >> lw, xe = rme & (W - 1);
            long long hb = (long long)off + ((long long)(ne * W2 + ye + 1) * W2 + xe + 1) * 256
                           + co0 + n_off + 2 * qd;
            long long sb2 = (long long)pe * 256 + co0 + n_off + 2 * qd;
#pragma unroll
            for (int ns = 0; ns < 8; ns++) {
                float v0 = a0c * fmaxf(acc[ms][ns][half * 2 + 0], 0.f);
                float v1 = a0c * fmaxf(acc[ms][ns][half * 2 + 1], 0.f);
                for (int d = nhist; d >= 1; d--) {
                    __nv_bfloat162 hv = *(const __nv_bfloat162*)&g_act[slots[d - 1]][hb + ns * 8];
                    v0 += coef[d - 1] * __bfloat162float(hv.x);
                    v1 += coef[d - 1] * __bfloat162float(hv.y);
                }
                *(float2*)&g_scratch[sb2 + ns * 8] = make_float2(v0, v1);
                cs[ns * 2 + 0] += v0;      cs[ns * 2 + 1] += v1;
                cq[ns * 2 + 0] += v0 * v0; cq[ns * 2 + 1] += v1 * v1;
            }
        }
    }
#pragma unroll
    for (int m = 4; m < 32; m <<= 1) {
#pragma unroll
        for (int j = 0; j < 16; j++) {
            cs[j] += __shfl_xor_sync(0xffffffffu, cs[j], m);
            cq[j] += __shfl_xor_sync(0xffffffffu, cq[j], m);
        }
    }
    if (lane < 4) {
#pragma unroll
        for (int ns = 0; ns < 8; ns++) {
            int ch = n_off + ns * 8 + 2 * lane;
            atomicAdd(&s_sum[ch],     cs[ns * 2 + 0]);
            atomicAdd(&s_sum[ch + 1], cs[ns * 2 + 1]);
            atomicAdd(&s_sq[ch],      cq[ns * 2 + 0]);
            atomicAdd(&s_sq[ch + 1],  cq[ns * 2 + 1]);
        }
    }
    __syncthreads();
    if (tid < 128) {
        atomicAdd(&g_sum[co0 + tid],   (double)s_sum[tid]);
        atomicAdd(&g_sqsum[co0 + tid], (double)s_sq[tid]);
    }
}

// stats + self-zero for next iteration
__global__ void k_stats(double invP) {
    int c = threadIdx.x;
    double mu  = g_sum[c] * invP;
    double var = g_sqsum[c] * invP - mu * mu;
    g_mu[c]   = (float)mu;
    g_rstd[c] = rsqrtf((float)var + 1e-5f);
    g_sum[c]   = 0.0;
    g_sqsum[c] = 0.0;
}

// BN + trunc-quantize (v=64) -> padded NHWC bf16 (zero halo)
__global__ void k_bnq(int sd, unsigned long long doff, int H, int W,
                      const float* __restrict__ gamma, const float* __restrict__ beta)
{
    int W2 = W + 2, H2 = H + 2;
    long long total = (long long)32 * H2 * W2 * 128;
    long long e = (long long)blockIdx.x * 256 + threadIdx.x;
    if (e >= total) return;
    int cp = (int)(e & 127); int c = cp * 2;
    long long r = e >> 7;
    int px = (int)(r % W2); r /= W2;
    int py = (int)(r % H2); int n = (int)(r / H2);
    __nv_bfloat162 outv;
    if (py >= 1 && py <= H && px >= 1 && px <= W) {
        const float2 v = *(const float2*)&g_scratch[((((long long)n * H + (py - 1)) * W + (px - 1)) << 8) + c];
        float b0 = gamma[c]     * ((v.x - g_mu[c])     * g_rstd[c])     + beta[c];
        float b1 = gamma[c + 1] * ((v.y - g_mu[c + 1]) * g_rstd[c + 1]) + beta[c + 1];
        outv.x = __float2bfloat16(truncf(b0 * 0.015625f) * 0.015625f);
        outv.y = __float2bfloat16(truncf(b1 * 0.015625f) * 0.015625f);
    } else {
        outv.x = __float2bfloat16(0.f);
        outv.y = __float2bfloat16(0.f);
    }
    *(__nv_bfloat162*)(&g_act[sd][doff + (e << 1)]) = outv;
}

// 2x2 maxpool of 4 slots at once (blockIdx.y selects slot from packed spack)
__global__ void k_pool4(int spack, unsigned long long soff, unsigned long long doff,
                        int H, int W)
{
    int s = (spack >> (blockIdx.y * 8)) & 0xff;
    int W2 = W + 2, H2 = H + 2, SW2 = 2 * W + 2;
    long long total = (long long)32 * H2 * W2 * 128;
    long long e = (long long)blockIdx.x * 256 + threadIdx.x;
    if (e >= total) return;
    int cp = (int)(e & 127);
    long long r = e >> 7;
    int px = (int)(r % W2); r /= W2;
    int py = (int)(r % H2); int n = (int)(r / H2);
    __nv_bfloat162 o;
    if (py >= 1 && py <= H && px >= 1 && px <= W) {
        const __nv_bfloat16* base = g_act[s] + soff;
        long long i00 = (((long long)n * (2 * H + 2) + (2 * py - 1)) * SW2 + (2 * px - 1)) * 256 + cp * 2;
        long long rs = (long long)SW2 * 256;
        __nv_bfloat162 v00 = *(const __nv_bfloat162*)(base + i00);
        __nv_bfloat162 v01 = *(const __nv_bfloat162*)(base + i00 + 256);
        __nv_bfloat162 v10 = *(const __nv_bfloat162*)(base + i00 + rs);
        __nv_bfloat162 v11 = *(const __nv_bfloat162*)(base + i00 + rs + 256);
        float m0 = fmaxf(fmaxf(__bfloat162float(v00.x), __bfloat162float(v01.x)),
                         fmaxf(__bfloat162float(v10.x), __bfloat162float(v11.x)));
        float m1 = fmaxf(fmaxf(__bfloat162float(v00.y), __bfloat162float(v01.y)),
                         fmaxf(__bfloat162float(v10.y), __bfloat162float(v11.y)));
        o.x = __float2bfloat16(m0);
        o.y = __float2bfloat16(m1);
    } else {
        o.x = __float2bfloat16(0.f);
        o.y = __float2bfloat16(0.f);
    }
    *(__nv_bfloat162*)(g_act[s] + doff + (e << 1)) = o;
}

__global__ void k_feat(int s, unsigned long long off) {
    int id = blockIdx.x * 256 + threadIdx.x;    // 32*256
    int n = id >> 8, c = id & 255;
    const __nv_bfloat16* base = g_act[s] + off;
    float m = -3.4e38f;
    for (int yy = 0; yy < 8; yy++)
        for (int xx = 0; xx < 8; xx++) {
            float v = __bfloat162float(base[(((long long)n * 10 + (yy + 1)) * 10 + (xx + 1)) * 256 + c]);
            m = fmaxf(m, v);
        }
    g_feat[id] = m;
}

__global__ void k_lin(const float* __restrict__ lw, const float* __restrict__ lb,
                      float* __restrict__ out) {
    __shared__ float fs[256];
    int n = blockIdx.y;
    int cls = blockIdx.x * 256 + threadIdx.x;
    fs[threadIdx.x] = g_feat[n * 256 + threadIdx.x];
    __syncthreads();
    if (cls < 1000) {
        float a = 0.f;
#pragma unroll 8
        for (int c = 0; c < 256; c++) a += fs[c] * lw[cls * 256 + c];
        out[n * 1000 + cls] = a + lb[cls];
    }
}

// ---------------------------------------------------------------------------
extern "C" void kernel_launch(void* const* d_in, const int* in_sizes, int n_in,
                              void* d_out, int out_size)
{
    const float* x      = (const float*)d_in[0];
    const float* conv_w = (const float*)d_in[1];
    const float* lin_w  = (const float*)d_in[2];
    const float* lin_b  = (const float*)d_in[3];
    const float* alpha  = (const float*)d_in[4];
    const float* gmm    = (const float*)d_in[5];
    const float* bta    = (const float*)d_in[6];
    float* out = (float*)d_out;

    k_prep_w<<<576, 256>>>(conv_w);
    k_prep_in<<<139392, 256>>>(x);

    static const int S1[10]  = {0,1,2,3,4,5,0,1,2,3};
    static const int S2[10]  = {0,0,1,2,3,4,5,0,1,2};
    static const int S3[10]  = {0,0,0,1,2,3,4,5,0,1};
    static const int S4[10]  = {0,0,0,0,1,2,3,4,5,0};
    static const int NH[10]  = {1,2,3,4,4,4,4,4,4,4};
    static const int DST[10] = {1,2,3,4,5,0,1,2,3,4};
    static const int HH[10]  = {64,64,64,32,32,32,16,16,16,8};
    static const int LW[10]  = {6,6,6,5,5,5,4,4,4,3};
    static const unsigned long long OFFT[10] =
        {OFF64,OFF64,OFF64,OFF32,OFF32,OFF32,OFF16,OFF16,OFF16,OFF8};

    for (int t = 0; t < 10; t++) {
        int H = HH[t], W = H, P = 32 * H * W;
        unsigned long long off = OFFT[t];
        dim3 cg(P / 128, 2);
        k_conv<<<cg, 256>>>(S1[t], S1[t], S2[t], S3[t], S4[t], NH[t],
                            off, LW[t], alpha, t);
        k_stats<<<1, 256>>>(1.0 / (double)P);
        long long tot = (long long)32 * (H + 2) * (W + 2) * 128;
        k_bnq<<<(unsigned)((tot + 255) / 256), 256>>>(DST[t], off, H, W,
                                                      gmm + t * 256, bta + t * 256);
        if (t == 2 || t == 5 || t == 8) {
            int Hd = H / 2, Wd = Hd;
            unsigned long long doff = (t == 2) ? OFF32 : (t == 5) ? OFF16 : OFF8;
            long long pt = (long long)32 * (Hd + 2) * (Wd + 2) * 128;
            int spack = (t == 5) ? (3 | (4 << 8) | (5 << 16) | (0 << 24))
                                 : (0 | (1 << 8) | (2 << 16) | (3 << 24));
            dim3 pg((unsigned)((pt + 255) / 256), 4);
            k_pool4<<<pg, 256>>>(spack, off, doff, Hd, Wd);
        }
    }
    k_feat<<<32, 256>>>(4, OFF8);
    k_lin<<<dim3(4, 32), 256>>>(lin_w, lin_b, out);
}

// round 5
// speedup vs baseline: 3.0903x; 1.1473x over previous
#include <cuda_runtime.h>
#include <cuda_bf16.h>
#include <cstdint>

// ---------------------------------------------------------------------------
// 6-slot ring of padded-NHWC bf16 activation buffers.
//   res64 @ 0, res32 @ 35,684,352, res16 @ 0, res8 @ 4,000,000
// ---------------------------------------------------------------------------
#define SLOT_ELEMS 45154304ull
#define OFF64 0ull
#define OFF32 35684352ull
#define OFF16 0ull
#define OFF8  4000000ull

__device__ __align__(16) __nv_bfloat16 g_act[6][SLOT_ELEMS];
__device__ __align__(16) float         g_scratch[33554432];   // fp32 pre-BN [pixel][256]
__device__ __align__(16) uint2         g_wf[147456];          // [tap][kc][nb][lane] B fragments
__device__ double g_sum[256];
__device__ double g_sqsum[256];
__device__ float  g_mu[256];
__device__ float  g_rstd[256];
__device__ float  g_feat[32 * 256];

__device__ __forceinline__ unsigned su32(const void* p) {
    return (unsigned)__cvta_generic_to_shared(p);
}

// conv_w (OIHW fp32, values = int/64) -> B-fragment layout:
// g_wf[((tap*16+kc)*32+nb)*32+lane] = {B[co=nb*8+g][k=kc*16+2qd..+1], [..+8..+9]}
__global__ void k_prep_w(const float* __restrict__ cw) {
    int idx = blockIdx.x * 256 + threadIdx.x;
    if (idx < 256) { g_sum[idx] = 0.0; g_sqsum[idx] = 0.0; }
    if (idx >= 147456) return;
    int l   = idx & 31;
    int nb  = (idx >> 5) & 31;
    int kc  = (idx >> 10) & 15;
    int tap = idx >> 14;
    int g = l >> 2, qd = l & 3;
    int co = nb * 8 + g, ci0 = kc * 16 + 2 * qd;
    __nv_bfloat162 lo, hi;
    lo.x = __float2bfloat16(cw[(co * 256 + ci0    ) * 9 + tap]);
    lo.y = __float2bfloat16(cw[(co * 256 + ci0 + 1) * 9 + tap]);
    hi.x = __float2bfloat16(cw[(co * 256 + ci0 + 8) * 9 + tap]);
    hi.y = __float2bfloat16(cw[(co * 256 + ci0 + 9) * 9 + tap]);
    uint2 v;
    v.x = *(unsigned*)&lo;
    v.y = *(unsigned*)&hi;
    g_wf[idx] = v;
}

// x (32,3,64,64) fp32 NCHW -> quantize (v=64), pad ch->256, padded NHWC bf16 slot0
__global__ void k_prep_in(const float* __restrict__ x) {
    long long e = (long long)blockIdx.x * 256 + threadIdx.x;
    if (e >= 35684352ll) return;
    int c = (int)(e & 255);
    long long r = e >> 8;
    int px = (int)(r % 66); r /= 66;
    int py = (int)(r % 66); int n = (int)(r / 66);
    float v = 0.f;
    if (py >= 1 && py <= 64 && px >= 1 && px <= 64 && c < 3) {
        float xv = x[(((long long)n * 3 + c) * 64 + (py - 1)) * 64 + (px - 1)];
        v = truncf(xv * 0.015625f) * 0.015625f;
    }
    g_act[0][e] = __float2bfloat16(v);
}

#define MMA_(c, a, b)                                                           \
    asm volatile("mma.sync.aligned.m16n8k16.row.col.f32.bf16.bf16.f32 "         \
                 "{%0,%1,%2,%3},{%4,%5,%6,%7},{%8,%9},{%0,%1,%2,%3};\n"         \
                 : "+f"(c[0]), "+f"(c[1]), "+f"(c[2]), "+f"(c[3])               \
                 : "r"(a[0]), "r"(a[1]), "r"(a[2]), "r"(a[3]),                  \
                   "r"(b.x), "r"(b.y))

// ---------------------------------------------------------------------------
// Big conv: kc-major. CTA 512 thr, tile M256 (pixels) x N128 (couts).
// 16 stages (one 16-ch chunk each): cp.async A slab (R+2 halo rows x W+2 x 16ch)
// + all 9 taps of B into double-buffered dynamic smem; 9 taps x 16 MMA per warp
// per stage. One __syncthreads per stage.
// ---------------------------------------------------------------------------
#define ASZ   12672                         // max A slab bytes (W=64: 6*66*32)
#define BSZ   36864                         // B stage bytes: 9*128*16*2
#define BB0_  (2*ASZ)
#define BB1_  (2*ASZ + BSZ)
#define DSM_TOTAL (2*ASZ + 2*BSZ)           // 99072

__global__ void __launch_bounds__(512) k_conv(
    int sPrev, int s1, int s2, int s3, int s4, int nhist,
    unsigned long long off, int lw,
    const float* __restrict__ alpha, int t)
{
    extern __shared__ __align__(16) char dynsmem[];
    __shared__ float s_sum[128], s_sq[128];

    const int tid = threadIdx.x, warp = tid >> 5, lane = tid & 31;
    const int g = lane >> 2, qd = lane & 3;
    const int mw = warp >> 1, nw = warp & 1;
    const int m_off = mw * 32, n_off = nw * 64;
    const int p0 = blockIdx.x * 256, co0 = blockIdx.y * 128;
    const int W = 1 << lw, W2 = W + 2, R = 256 >> lw;

    if (tid < 128) { s_sum[tid] = 0.f; s_sq[tid] = 0.f; }

    const int n_img = p0 >> (2 * lw);
    const int y0    = (p0 >> lw) & (W - 1);
    const char* aBase = (const char*)(g_act[sPrev] + off);

    // --- per-thread A chunks (16B each): entry=(ry*W2+cx), two halves ---
    const int nA = (R + 2) * W2 * 2;
    int aSrc[2]; unsigned aDst[2]; int aCnt = 0;
#pragma unroll
    for (int k = 0; k < 2; k++) {
        int c = tid + k * 512;
        if (c < nA) {
            int entry = c >> 1, half = c & 1;
            int ry = entry / W2, cx = entry - ry * W2;
            aSrc[aCnt] = ((n_img * W2 + y0 + ry) * W2 + cx) * 512 + half * 16;
            aDst[aCnt] = (unsigned)(entry * 32 + ((half ^ ((cx >> 2) & 1)) << 4));
            aCnt++;
        }
    }
    // --- per-thread B chunks (16B each): 2304 total ---
    const int nb0 = co0 >> 3;
    int bSrc[5]; unsigned bDst[5]; int bCnt = 0;
#pragma unroll
    for (int k = 0; k < 5; k++) {
        int c = tid + k * 512;
        if (c < 2304) {
            int tap = c >> 8, rest = c & 255;
            bSrc[bCnt] = tap * 16384 + nb0 * 32 + rest * 2;   // uint2 index (add kc*1024)
            bDst[bCnt] = (unsigned)(tap * 4096 + rest * 16);
            bCnt++;
        }
    }

    const unsigned smbase = su32(dynsmem);

#define ISSUE(kc_, Ao_, Bo_) {                                                  \
    for (int a_ = 0; a_ < aCnt; a_++) {                                         \
        unsigned d_ = smbase + (Ao_) + aDst[a_];                                \
        const char* s_ = aBase + aSrc[a_] + (kc_) * 32;                         \
        asm volatile("cp.async.cg.shared.global [%0],[%1],16;\n" :: "r"(d_), "l"(s_)); } \
    for (int b_ = 0; b_ < bCnt; b_++) {                                         \
        unsigned d_ = smbase + (Bo_) + bDst[b_];                                \
        const char* s_ = (const char*)(g_wf + bSrc[b_] + (kc_) * 1024);         \
        asm volatile("cp.async.cg.shared.global [%0],[%1],16;\n" :: "r"(d_), "l"(s_)); } \
    asm volatile("cp.async.commit_group;\n"); }

    // ldmatrix per-tile precompute
    const int pt0 = m_off + (lane & 15);
    const int ry0 = pt0 >> lw, x0 = pt0 & (W - 1);
    const int e0  = ry0 * W2 + x0;
    const int pt1 = pt0 + 16;
    const int ry1 = pt1 >> lw, x1 = pt1 & (W - 1);
    const int e1  = ry1 * W2 + x1;
    const int hh  = lane >> 4;

    float acc[2][8][4];
#pragma unroll
    for (int i = 0; i < 2; i++)
#pragma unroll
        for (int j = 0; j < 8; j++)
#pragma unroll
            for (int k = 0; k < 4; k++) acc[i][j][k] = 0.f;

    ISSUE(0, 0, BB0_);

    for (int kc = 0; kc < 16; kc++) {
        int cur = kc & 1;
        if (kc < 15) {
            if (cur) { ISSUE(kc + 1, 0,   BB0_); }
            else     { ISSUE(kc + 1, ASZ, BB1_); }
            asm volatile("cp.async.wait_group 1;\n" ::);
        } else {
            asm volatile("cp.async.wait_group 0;\n" ::);
        }
        __syncthreads();

        const unsigned Ac = smbase + (cur ? ASZ : 0);
        const char*    Bc = dynsmem + (cur ? BB1_ : BB0_);

#pragma unroll
        for (int tap = 0; tap < 9; tap++) {
            const int ky = tap / 3, kx = tap - 3 * (tap / 3);
            uint2 bq[8];
            const uint2* bp = (const uint2*)(Bc + tap * 4096 + nw * 2048 + lane * 8);
#pragma unroll
            for (int j = 0; j < 8; j++) bq[j] = bp[j * 32];

            unsigned am0[4], am1[4];
            {
                int cx = x0 + kx;
                unsigned ad = Ac + (unsigned)((e0 + ky * W2 + kx) * 32)
                                 + (unsigned)((hh ^ ((cx >> 2) & 1)) << 4);
                asm volatile("ldmatrix.sync.aligned.m8n8.x4.shared.b16 {%0,%1,%2,%3},[%4];\n"
                             : "=r"(am0[0]), "=r"(am0[1]), "=r"(am0[2]), "=r"(am0[3]) : "r"(ad));
            }
            {
                int cx = x1 + kx;
                unsigned ad = Ac + (unsigned)((e1 + ky * W2 + kx) * 32)
                                 + (unsigned)((hh ^ ((cx >> 2) & 1)) << 4);
                asm volatile("ldmatrix.sync.aligned.m8n8.x4.shared.b16 {%0,%1,%2,%3},[%4];\n"
                             : "=r"(am1[0]), "=r"(am1[1]), "=r"(am1[2]), "=r"(am1[3]) : "r"(ad));
            }
#pragma unroll
            for (int ns = 0; ns < 8; ns++) {
                MMA_(acc[0][ns], am0, bq[ns]);
                MMA_(acc[1][ns], am1, bq[ns]);
            }
        }
    }
#undef ISSUE

    // ---- register-space epilogue ----
    const float a0c = alpha[t * 6];
    int slots[4] = { s1, s2, s3, s4 };
    float coef[4] = { 0.f, 0.f, 0.f, 0.f };
    for (int d = 1; d <= nhist; d++) coef[d - 1] = alpha[t * 6 + 6 - d];

    float cs[16], cq[16];
#pragma unroll
    for (int j = 0; j < 16; j++) { cs[j] = 0.f; cq[j] = 0.f; }

#pragma unroll
    for (int ms = 0; ms < 2; ms++) {
#pragma unroll
        for (int half = 0; half < 2; half++) {
            int pe  = p0 + m_off + ms * 16 + g + half * 8;
            int ne  = pe >> (2 * lw);
            int rme = pe & ((1 << (2 * lw)) - 1);
            int ye = rme >> lw, xe = rme & (W - 1);
            long long hb = (long long)off + ((long long)(ne * W2 + ye + 1) * W2 + xe + 1) * 256
                           + co0 + n_off + 2 * qd;
            long long sb2 = (long long)pe * 256 + co0 + n_off + 2 * qd;
#pragma unroll
            for (int ns = 0; ns < 8; ns++) {
                float v0 = a0c * fmaxf(acc[ms][ns][half * 2 + 0], 0.f);
                float v1 = a0c * fmaxf(acc[ms][ns][half * 2 + 1], 0.f);
                for (int d = nhist; d >= 1; d--) {
                    __nv_bfloat162 hv = *(const __nv_bfloat162*)&g_act[slots[d - 1]][hb + ns * 8];
                    v0 += coef[d - 1] * __bfloat162float(hv.x);
                    v1 += coef[d - 1] * __bfloat162float(hv.y);
                }
                *(float2*)&g_scratch[sb2 + ns * 8] = make_float2(v0, v1);
                cs[ns * 2 + 0] += v0;      cs[ns * 2 + 1] += v1;
                cq[ns * 2 + 0] += v0 * v0; cq[ns * 2 + 1] += v1 * v1;
            }
        }
    }
#pragma unroll
    for (int m = 4; m < 32; m <<= 1) {
#pragma unroll
        for (int j = 0; j < 16; j++) {
            cs[j] += __shfl_xor_sync(0xffffffffu, cs[j], m);
            cq[j] += __shfl_xor_sync(0xffffffffu, cq[j], m);
        }
    }
    if (lane < 4) {
#pragma unroll
        for (int ns = 0; ns < 8; ns++) {
            int ch = n_off + ns * 8 + 2 * lane;
            atomicAdd(&s_sum[ch],     cs[ns * 2 + 0]);
            atomicAdd(&s_sum[ch + 1], cs[ns * 2 + 1]);
            atomicAdd(&s_sq[ch],      cq[ns * 2 + 0]);
            atomicAdd(&s_sq[ch + 1],  cq[ns * 2 + 1]);
        }
    }
    __syncthreads();
    if (tid < 128) {
        atomicAdd(&g_sum[co0 + tid],   (double)s_sum[tid]);
        atomicAdd(&g_sqsum[co0 + tid], (double)s_sq[tid]);
    }
}

// ---------------------------------------------------------------------------
// Small conv (res8 only): R4 tap-major kernel. CTA 256 thr, M128 x N128.
// ---------------------------------------------------------------------------
__global__ void __launch_bounds__(256, 2) k_conv_small(
    int sPrev, int s1, int s2, int s3, int s4, int nhist,
    unsigned long long off, int lw,
    const float* __restrict__ alpha, int t)
{
    constexpr int S   = 144;
    constexpr int STB = 4096;
    __shared__ __align__(256) char As[3 * STB];
    __shared__ float s_sum[128], s_sq[128];

    const int tid = threadIdx.x, warp = tid >> 5, lane = tid & 31;
    const int g = lane >> 2, qd = lane & 3;
    const int mw = warp >> 1, nw = warp & 1;
    const int m_off = mw * 32, n_off = nw * 64;
    const int p0 = blockIdx.x * 128, co0 = blockIdx.y * 128;
    const int W = 1 << lw, W2 = W + 2;

    if (tid < 128) { s_sum[tid] = 0.f; s_sq[tid] = 0.f; }

    const int r = tid >> 1, h = tid & 1;
    int p  = p0 + r;
    int n  = p >> (2 * lw);
    int rm = p & ((1 << (2 * lw)) - 1);
    int yy = rm >> lw, xx = rm & (W - 1);
    const __nv_bfloat16* hp = g_act[sPrev] + off;
    const char* rowp[3];
#pragma unroll
    for (int ky = 0; ky < 3; ky++)
        rowp[ky] = (const char*)(hp + ((long long)(n * W2 + yy + ky) * W2 + xx) * 256 + h * 8);

    const int rr = r & 7;
    const unsigned dstb = su32(As) + (r >> 3) * 256 + ((rr * 2 + (h ^ ((rr >> 2) & 1))) << 4);
    const int rl = m_off + (lane & 15), hh = lane >> 4, rlr = rl & 7;
    const unsigned ldsb = su32(As) + (rl >> 3) * 256 + ((rlr * 2 + (hh ^ ((rlr >> 2) & 1))) << 4);
    const int nb0 = (co0 >> 3) + nw * 8;

#define CPA(s_, ph_) {                                                          \
    int tap_ = (s_) >> 4, kc_ = (s_) & 15;                                      \
    int ky_ = (tap_ * 11) >> 5; int kx_ = tap_ - 3 * ky_;                       \
    const char* src_ = rowp[ky_] + kx_ * 512 + kc_ * 32;                        \
    asm volatile("cp.async.cg.shared.global [%0],[%1],16;\n"                    \
                 :: "r"(dstb + (ph_) * STB), "l"(src_));                        \
    asm volatile("cp.async.commit_group;\n"); }

#define LDB(dst) {                                                              \
    dst[0] = wptr[0];   dst[1] = wptr[32];  dst[2] = wptr[64];  dst[3] = wptr[96]; \
    dst[4] = wptr[128]; dst[5] = wptr[160]; dst[6] = wptr[192]; dst[7] = wptr[224]; \
    wptr += 1024; }

    float acc[2][8][4];
#pragma unroll
    for (int i = 0; i < 2; i++)
#pragma unroll
        for (int j = 0; j < 8; j++)
#pragma unroll
            for (int k = 0; k < 4; k++) acc[i][j][k] = 0.f;

    uint2 bA[8], bB[8];
    const uint2* wptr = g_wf + (nb0 << 5) + lane;
    LDB(bA);
    CPA(0, 0); CPA(1, 1);

#define BODY(j_, CUR, NXT) {                                                    \
    int s_ = sb + (j_);                                                         \
    if (s_ == S - 1) asm volatile("cp.async.wait_group 0;\n" ::);               \
    else             asm volatile("cp.async.wait_group 1;\n" ::);               \
    __syncthreads();                                                            \
    if (s_ + 2 < S) CPA(s_ + 2, ((j_) + 2) % 3);                                \
    if (s_ + 1 < S) LDB(NXT);                                                   \
    unsigned a0[4], a1[4];                                                      \
    unsigned base_ = ldsb + ((j_) % 3) * STB;                                   \
    asm volatile("ldmatrix.sync.aligned.m8n8.x4.shared.b16 {%0,%1,%2,%3},[%4];\n" \
                 : "=r"(a0[0]), "=r"(a0[1]), "=r"(a0[2]), "=r"(a0[3]) : "r"(base_)); \
    asm volatile("ldmatrix.sync.aligned.m8n8.x4.shared.b16 {%0,%1,%2,%3},[%4];\n" \
                 : "=r"(a1[0]), "=r"(a1[1]), "=r"(a1[2]), "=r"(a1[3]) : "r"(base_ + 512)); \
    _Pragma("unroll")                                                           \
    for (int ns = 0; ns < 8; ns++) {                                            \
        MMA_(acc[0][ns], a0, CUR[ns]);                                          \
        MMA_(acc[1][ns], a1, CUR[ns]);                                          \
    } }

    for (int sb = 0; sb < S; sb += 6) {
        BODY(0, bA, bB); BODY(1, bB, bA); BODY(2, bA, bB);
        BODY(3, bB, bA); BODY(4, bA, bB); BODY(5, bB, bA);
    }
#undef BODY
#undef CPA
#undef LDB

    const float a0c = alpha[t * 6];
    int slots[4] = { s1, s2, s3, s4 };
    float coef[4] = { 0.f, 0.f, 0.f, 0.f };
    for (int d = 1; d <= nhist; d++) coef[d - 1] = alpha[t * 6 + 6 - d];

    float cs[16], cq[16];
#pragma unroll
    for (int j = 0; j < 16; j++) { cs[j] = 0.f; cq[j] = 0.f; }

#pragma unroll
    for (int ms = 0; ms < 2; ms++) {
#pragma unroll
        for (int half = 0; half < 2; half++) {
            int pe  = p0 + m_off + ms * 16 + g + half * 8;
            int ne  = pe >> (2 * lw);
            int rme = pe & ((1 << (2 * lw)) - 1);
            int ye = rme >> lw, xe = rme & (W - 1);
            long long hb = (long long)off + ((long long)(ne * W2 + ye + 1) * W2 + xe + 1) * 256
                           + co0 + n_off + 2 * qd;
            long long sb2 = (long long)pe * 256 + co0 + n_off + 2 * qd;
#pragma unroll
            for (int ns = 0; ns < 8; ns++) {
                float v0 = a0c * fmaxf(acc[ms][ns][half * 2 + 0], 0.f);
                float v1 = a0c * fmaxf(acc[ms][ns][half * 2 + 1], 0.f);
                for (int d = nhist; d >= 1; d--) {
                    __nv_bfloat162 hv = *(const __nv_bfloat162*)&g_act[slots[d - 1]][hb + ns * 8];
                    v0 += coef[d - 1] * __bfloat162float(hv.x);
                    v1 += coef[d - 1] * __bfloat162float(hv.y);
                }
                *(float2*)&g_scratch[sb2 + ns * 8] = make_float2(v0, v1);
                cs[ns * 2 + 0] += v0;      cs[ns * 2 + 1] += v1;
                cq[ns * 2 + 0] += v0 * v0; cq[ns * 2 + 1] += v1 * v1;
            }
        }
    }
#pragma unroll
    for (int m = 4; m < 32; m <<= 1) {
#pragma unroll
        for (int j = 0; j < 16; j++) {
            cs[j] += __shfl_xor_sync(0xffffffffu, cs[j], m);
            cq[j] += __shfl_xor_sync(0xffffffffu, cq[j], m);
        }
    }
    if (lane < 4) {
#pragma unroll
        for (int ns = 0; ns < 8; ns++) {
            int ch = n_off + ns * 8 + 2 * lane;
            atomicAdd(&s_sum[ch],     cs[ns * 2 + 0]);
            atomicAdd(&s_sum[ch + 1], cs[ns * 2 + 1]);
            atomicAdd(&s_sq[ch],      cq[ns * 2 + 0]);
            atomicAdd(&s_sq[ch + 1],  cq[ns * 2 + 1]);
        }
    }
    __syncthreads();
    if (tid < 128) {
        atomicAdd(&g_sum[co0 + tid],   (double)s_sum[tid]);
        atomicAdd(&g_sqsum[co0 + tid], (double)s_sq[tid]);
    }
}

// stats + self-zero for next iteration
__global__ void k_stats(double invP) {
    int c = threadIdx.x;
    double mu  = g_sum[c] * invP;
    double var = g_sqsum[c] * invP - mu * mu;
    g_mu[c]   = (float)mu;
    g_rstd[c] = rsqrtf((float)var + 1e-5f);
    g_sum[c]   = 0.0;
    g_sqsum[c] = 0.0;
}

// BN + trunc-quantize (v=64) -> padded NHWC bf16 (zero halo)
__global__ void k_bnq(int sd, unsigned long long doff, int H, int W,
                      const float* __restrict__ gamma, const float* __restrict__ beta)
{
    int W2 = W + 2, H2 = H + 2;
    long long total = (long long)32 * H2 * W2 * 128;
    long long e = (long long)blockIdx.x * 256 + threadIdx.x;
    if (e >= total) return;
    int cp = (int)(e & 127); int c = cp * 2;
    long long r = e >> 7;
    int px = (int)(r % W2); r /= W2;
    int py = (int)(r % H2); int n = (int)(r / H2);
    __nv_bfloat162 outv;
    if (py >= 1 && py <= H && px >= 1 && px <= W) {
        const float2 v = *(const float2*)&g_scratch[((((long long)n * H + (py - 1)) * W + (px - 1)) << 8) + c];
        float b0 = gamma[c]     * ((v.x - g_mu[c])     * g_rstd[c])     + beta[c];
        float b1 = gamma[c + 1] * ((v.y - g_mu[c + 1]) * g_rstd[c + 1]) + beta[c + 1];
        outv.x = __float2bfloat16(truncf(b0 * 0.015625f) * 0.015625f);
        outv.y = __float2bfloat16(truncf(b1 * 0.015625f) * 0.015625f);
    } else {
        outv.x = __float2bfloat16(0.f);
        outv.y = __float2bfloat16(0.f);
    }
    *(__nv_bfloat162*)(&g_act[sd][doff + (e << 1)]) = outv;
}

// 2x2 maxpool of 4 slots at once
__global__ void k_pool4(int spack, unsigned long long soff, unsigned long long doff,
                        int H, int W)
{
    int s = (spack >> (blockIdx.y * 8)) & 0xff;
    int W2 = W + 2, H2 = H + 2, SW2 = 2 * W + 2;
    long long total = (long long)32 * H2 * W2 * 128;
    long long e = (long long)blockIdx.x * 256 + threadIdx.x;
    if (e >= total) return;
    int cp = (int)(e & 127);
    long long r = e >> 7;
    int px = (int)(r % W2); r /= W2;
    int py = (int)(r % H2); int n = (int)(r / H2);
    __nv_bfloat162 o;
    if (py >= 1 && py <= H && px >= 1 && px <= W) {
        const __nv_bfloat16* base = g_act[s] + soff;
        long long i00 = (((long long)n * (2 * H + 2) + (2 * py - 1)) * SW2 + (2 * px - 1)) * 256 + cp * 2;
        long long rs = (long long)SW2 * 256;
        __nv_bfloat162 v00 = *(const __nv_bfloat162*)(base + i00);
        __nv_bfloat162 v01 = *(const __nv_bfloat162*)(base + i00 + 256);
        __nv_bfloat162 v10 = *(const __nv_bfloat162*)(base + i00 + rs);
        __nv_bfloat162 v11 = *(const __nv_bfloat162*)(base + i00 + rs + 256);
        float m0 = fmaxf(fmaxf(__bfloat162float(v00.x), __bfloat162float(v01.x)),
                         fmaxf(__bfloat162float(v10.x), __bfloat162float(v11.x)));
        float m1 = fmaxf(fmaxf(__bfloat162float(v00.y), __bfloat162float(v01.y)),
                         fmaxf(__bfloat162float(v10.y), __bfloat162float(v11.y)));
        o.x = __float2bfloat16(m0);
        o.y = __float2bfloat16(m1);
    } else {
        o.x = __float2bfloat16(0.f);
        o.y = __float2bfloat16(0.f);
    }
    *(__nv_bfloat162*)(g_act[s] + doff + (e << 1)) = o;
}

__global__ void k_feat(int s, unsigned long long off) {
    int id = blockIdx.x * 256 + threadIdx.x;    // 32*256
    int n = id >> 8, c = id & 255;
    const __nv_bfloat16* base = g_act[s] + off;
    float m = -3.4e38f;
    for (int yy = 0; yy < 8; yy++)
        for (int xx = 0; xx < 8; xx++) {
            float v = __bfloat162float(base[(((long long)n * 10 + (yy + 1)) * 10 + (xx + 1)) * 256 + c]);
            m = fmaxf(m, v);
        }
    g_feat[id] = m;
}

__global__ void k_lin(const float* __restrict__ lw, const float* __restrict__ lb,
                      float* __restrict__ out) {
    __shared__ float fs[256];
    int n = blockIdx.y;
    int cls = blockIdx.x * 256 + threadIdx.x;
    fs[threadIdx.x] = g_feat[n * 256 + threadIdx.x];
    __syncthreads();
    if (cls < 1000) {
        float a = 0.f;
#pragma unroll 8
        for (int c = 0; c < 256; c++) a += fs[c] * lw[cls * 256 + c];
        out[n * 1000 + cls] = a + lb[cls];
    }
}

// ---------------------------------------------------------------------------
extern "C" void kernel_launch(void* const* d_in, const int* in_sizes, int n_in,
                              void* d_out, int out_size)
{
    const float* x      = (const float*)d_in[0];
    const float* conv_w = (const float*)d_in[1];
    const float* lin_w  = (const float*)d_in[2];
    const float* lin_b  = (const float*)d_in[3];
    const float* alpha  = (const float*)d_in[4];
    const float* gmm    = (const float*)d_in[5];
    const float* bta    = (const float*)d_in[6];
    float* out = (float*)d_out;

    cudaFuncSetAttribute(k_conv, cudaFuncAttributeMaxDynamicSharedMemorySize, DSM_TOTAL);

    k_prep_w<<<576, 256>>>(conv_w);
    k_prep_in<<<139392, 256>>>(x);

    static const int S1[10]  = {0,1,2,3,4,5,0,1,2,3};
    static const int S2[10]  = {0,0,1,2,3,4,5,0,1,2};
    static const int S3[10]  = {0,0,0,1,2,3,4,5,0,1};
    static const int S4[10]  = {0,0,0,0,1,2,3,4,5,0};
    static const int NH[10]  = {1,2,3,4,4,4,4,4,4,4};
    static const int DST[10] = {1,2,3,4,5,0,1,2,3,4};
    static const int HH[10]  = {64,64,64,32,32,32,16,16,16,8};
    static const int LW[10]  = {6,6,6,5,5,5,4,4,4,3};
    static const unsigned long long OFFT[10] =
        {OFF64,OFF64,OFF64,OFF32,OFF32,OFF32,OFF16,OFF16,OFF16,OFF8};

    for (int t = 0; t < 10; t++) {
        int H = HH[t], W = H, P = 32 * H * W;
        unsigned long long off = OFFT[t];
        if (t < 9) {
            dim3 cg(P / 256, 2);
            k_conv<<<cg, 512, DSM_TOTAL>>>(S1[t], S1[t], S2[t], S3[t], S4[t], NH[t],
                                           off, LW[t], alpha, t);
        } else {
            dim3 cg(P / 128, 2);
            k_conv_small<<<cg, 256>>>(S1[t], S1[t], S2[t], S3[t], S4[t], NH[t],
                                      off, LW[t], alpha, t);
        }
        k_stats<<<1, 256>>>(1.0 / (double)P);
        long long tot = (long long)32 * (H + 2) * (W + 2) * 128;
        k_bnq<<<(unsigned)((tot + 255) / 256), 256>>>(DST[t], off, H, W,
                                                      gmm + t * 256, bta + t * 256);
        if (t == 2 || t == 5 || t == 8) {
            int Hd = H / 2, Wd = Hd;
            unsigned long long doff = (t == 2) ? OFF32 : (t == 5) ? OFF16 : OFF8;
            long long pt = (long long)32 * (Hd + 2) * (Wd + 2) * 128;
            int spack = (t == 5) ? (3 | (4 << 8) | (5 << 16) | (0 << 24))
                                 : (0 | (1 << 8) | (2 << 16) | (3 << 24));
            dim3 pg((unsigned)((pt + 255) / 256), 4);
            k_pool4<<<pg, 256>>>(spack, off, doff, Hd, Wd);
        }
    }
    k_feat<<<32, 256>>>(4, OFF8);
    k_lin<<<dim3(4, 32), 256>>>(lin_w, lin_b, out);
}